// round 3
// baseline (speedup 1.0000x reference)
#include <cuda_runtime.h>
#include <cuda_bf16.h>
#include <cub/cub.cuh>

#define CH 1024
constexpr int MAXN = 1 << 18;
constexpr int MAXC = MAXN / CH;

__device__ float  g_proj[MAXN];
__device__ float  g_sorted[MAXN];
__device__ double g_xs[MAXN + 2];
__device__ int    g_lh_idx[MAXN];
__device__ double g_lh_val[MAXN];
__device__ int    g_lhn[MAXC];
__device__ int    g_uh_idx[MAXN];
__device__ double g_uh_val[MAXN];
__device__ int    g_uhn[MAXC];
__device__ int    g_Hidx[MAXN + 2];
__device__ double g_Hval[MAXN + 2];
__device__ int    g_Sidx[MAXN + 2];
__device__ double g_Sval[MAXN + 2];
__device__ int    g_gcm[MAXN + 2];
__device__ int    g_lcm[MAXN + 2];
__device__ unsigned char g_cub_tmp[1 << 24];

// ---------------- matvec: one warp per row, D=128 ----------------
__global__ void k_matvec(const float* __restrict__ X, const float* __restrict__ PV,
                         const int* __restrict__ IDX, int N) {
    __shared__ __align__(16) float sp[128];
    int pidx = IDX[0];
    if (threadIdx.x < 128) sp[threadIdx.x] = PV[pidx * 128 + threadIdx.x];
    __syncthreads();
    int g    = blockIdx.x * blockDim.x + threadIdx.x;
    int row  = g >> 5;
    int lane = g & 31;
    if (row >= N) return;
    const float4* xr = reinterpret_cast<const float4*>(X) + (size_t)row * 32;
    float4 a = xr[lane];
    float4 b = reinterpret_cast<const float4*>(sp)[lane];
    float s = a.x * b.x + a.y * b.y + a.z * b.z + a.w * b.w;
#pragma unroll
    for (int o = 16; o; o >>= 1) s += __shfl_xor_sync(0xffffffffu, s, o);
    if (lane == 0) g_proj[row] = s;
}

__global__ void k_convert(int N) {
    int i = blockIdx.x * blockDim.x + threadIdx.x;
    if (i < N) g_xs[i + 1] = (double)g_sorted[i];
    if (i == 0) g_xs[0] = 0.0;
}

// Strict monotone-chain push; pop inequality is the exact one from the
// reference (equality pops -> collinear mid-points removed). Works for the
// upper hull when candidates are fed right-to-left (both index deltas flip).
__device__ __forceinline__ void hull_push(int ci, double cv, int* sidx, double* sval,
                                          int& m, int& ai, int& bi, double& av, double& bv) {
    while (m >= 2) {
        if ((cv - bv) * (double)(bi - ai) < (bv - av) * (double)(ci - bi)) break;
        m--; bi = ai; bv = av;
        if (m >= 2) { ai = sidx[m - 2]; av = sval[m - 2]; }
    }
    sidx[m] = ci; sval[m] = cv;
    ai = bi; av = bv; bi = ci; bv = cv; m++;
}

__global__ void k_chunk_hulls(int N) {
    int c = blockIdx.x;
    int s = c * CH + 1;
    int e = (c + 1) * CH; if (e > N) e = N;
    int base = c * CH;
    if (threadIdx.x == 0) {
        int m = 0, ai = 0, bi = 0; double av = 0.0, bv = 0.0;
        for (int i = s; i <= e; i++)
            hull_push(i, g_xs[i], g_lh_idx + base, g_lh_val + base, m, ai, bi, av, bv);
        g_lhn[c] = m;
    } else if (threadIdx.x == 32) {
        int m = 0, ai = 0, bi = 0; double av = 0.0, bv = 0.0;
        for (int i = e; i >= s; i--)
            hull_push(i, g_xs[i], g_uh_idx + base, g_uh_val + base, m, ai, bi, av, bv);
        g_uhn[c] = m;   // stored in decreasing-index (push) order
    }
}

__device__ __forceinline__ double block_max(double v, double* red, int tid) {
    red[tid] = v;
    __syncthreads();
    for (int s = 512; s > 0; s >>= 1) {
        if (tid < s) { double o = red[tid + s]; if (o > red[tid]) red[tid] = o; }
        __syncthreads();
    }
    double r = red[0];
    __syncthreads();
    return r;
}

__global__ void __launch_bounds__(1024, 1) k_dip(int N, float* out) {
    __shared__ double red[1024];
    __shared__ int s_low, s_high, s_lgcm, s_llcm, s_ig, s_ih, s_done;
    __shared__ double s_dip;
    int tid = threadIdx.x;
    if (tid == 0) { s_low = 1; s_high = N; s_dip = 1.0; s_done = 0; }
    __syncthreads();

    if (N < 4 || g_xs[1] == g_xs[N]) {
        if (tid == 0) out[0] = (float)(1.0 / (2.0 * (double)(N > 0 ? N : 1)));
        return;
    }
    int nchunk = (N + CH - 1) / CH;

    for (int iter = 0; iter < 64; iter++) {
        int low = s_low, high = s_high;

        if (tid == 0) {
            // gcm chain = strict lower hull of [1..high], via chunk-hull merge
            int m = 0, ai = 0, bi = 0; double av = 0.0, bv = 0.0;
            int hc = (high - 1) / CH;
            for (int c = 0; c < hc; c++) {
                int base = c * CH, n = g_lhn[c];
                for (int t = 0; t < n; t++)
                    hull_push(g_lh_idx[base + t], g_lh_val[base + t],
                              g_Hidx, g_Hval, m, ai, bi, av, bv);
            }
            for (int ci = hc * CH + 1; ci <= high; ci++)
                hull_push(ci, g_xs[ci], g_Hidx, g_Hval, m, ai, bi, av, bv);
            // largest t with Hidx[t] <= low (Hidx[0] = 1 <= low always)
            int lo2 = 0, hi2 = m - 1;
            while (lo2 < hi2) {
                int mid = (lo2 + hi2 + 1) >> 1;
                if (g_Hidx[mid] <= low) lo2 = mid; else hi2 = mid - 1;
            }
            int lg = m - lo2;
            for (int i = 1; i <= lg; i++) g_gcm[i] = g_Hidx[m - i]; // gcm[1]=high
            g_gcm[0] = 0;
            s_lgcm = lg;
        }
        if (tid == 32) {
            // lcm chain = strict upper hull of [low..N], built right-to-left
            int m = 0, ai = 0, bi = 0; double av = 0.0, bv = 0.0;
            int lc = (low - 1) / CH;
            for (int c = nchunk - 1; c > lc; c--) {
                int base = c * CH, n = g_uhn[c];
                for (int t = 0; t < n; t++)
                    hull_push(g_uh_idx[base + t], g_uh_val[base + t],
                              g_Sidx, g_Sval, m, ai, bi, av, bv);
            }
            int e = (lc + 1) * CH; if (e > N) e = N;
            for (int ci = e; ci >= low; ci--)
                hull_push(ci, g_xs[ci], g_Sidx, g_Sval, m, ai, bi, av, bv);
            // largest t with Sidx[t] >= high (Sidx[0] = N >= high always)
            int lo2 = 0, hi2 = m - 1;
            while (lo2 < hi2) {
                int mid = (lo2 + hi2 + 1) >> 1;
                if (g_Sidx[mid] >= high) lo2 = mid; else hi2 = mid - 1;
            }
            int ll = m - lo2;
            for (int i = 1; i <= ll; i++) g_lcm[i] = g_Sidx[m - i]; // lcm[1]=low
            g_lcm[0] = 0;
            s_llcm = ll;
        }
        __syncthreads();

        if (tid == 0) {
            // d-walk: verbatim port
            int lg = s_lgcm, ll = s_llcm;
            int ig = lg, ih = ll, ix = ig - 1, iv = 2;
            double d = 0.0;
            if (!(lg == 2 && ll == 2)) {
                long long guard = 4LL * N + 16;
                while (guard-- > 0) {
                    int gcmix = g_gcm[ix], lcmiv = g_lcm[iv];
                    if (gcmix > lcmiv) {
                        int gcmi1 = g_gcm[ix + 1];
                        double t = (double)(lcmiv - gcmi1 + 1)
                                 - (g_xs[lcmiv] - g_xs[gcmi1]) * (double)(gcmix - gcmi1)
                                   / (g_xs[gcmix] - g_xs[gcmi1]);
                        iv++;
                        if (t >= d) { d = t; ig = ix + 1; ih = iv - 1; }
                    } else {
                        int lcmiv1 = g_lcm[iv - 1];
                        double t = (g_xs[gcmix] - g_xs[lcmiv1]) * (double)(lcmiv - lcmiv1)
                                   / (g_xs[lcmiv] - g_xs[lcmiv1])
                                 - (double)(gcmix - lcmiv1 - 1);
                        ix--;
                        if (t > d) { d = t; ig = ix + 1; ih = iv; }
                    }
                    if (ix < 1) ix = 1;
                    if (iv > ll) iv = ll;
                    if (g_gcm[ix] == g_lcm[iv]) break;
                }
            } else {
                d = 1.0;
            }
            s_ig = ig; s_ih = ih;
            if (d < s_dip) s_done = 1;
        }
        __syncthreads();
        if (s_done) break;

        // fused parallel segment scans (only the max matters)
        int lg = s_lgcm, ll = s_llcm, ig = s_ig, ih = s_ih;
        double lmax = -1e308, umax = -1e308;

        if (lg > ig) {  // lower segments cover [gcm[lg], gcm[ig]]
            int A = g_gcm[lg], B = g_gcm[ig];
            int total = B - A + 1;
            int per = (total + 1023) / 1024;
            int lo = A + tid * per;
            int hi = lo + per - 1; if (hi > B) hi = B;
            if (lo <= hi) {
                int nseg = lg - ig;
                int lo2 = 0, hi2 = nseg - 1;
                while (lo2 < hi2) {
                    int mid = (lo2 + hi2 + 1) >> 1;
                    if (g_gcm[lg - mid] <= lo) lo2 = mid; else hi2 = mid - 1;
                }
                int t = lo2;
                int jb = g_gcm[lg - t], je = g_gcm[lg - t - 1];
                double xjb = g_xs[jb], xje = g_xs[je];
                bool valid = (je - jb > 1) && (xje != xjb);
                double C = valid ? (double)(je - jb) / (xje - xjb) : 0.0;
                for (int i = lo; i <= hi; i++) {
                    while (i > je && t < nseg - 1) {
                        t++; jb = je; xjb = xje;
                        je = g_gcm[lg - t - 1]; xje = g_xs[je];
                        valid = (je - jb > 1) && (xje != xjb);
                        C = valid ? (double)(je - jb) / (xje - xjb) : 0.0;
                    }
                    if (valid) {
                        double tt = (double)(i - jb + 1) - (g_xs[i] - xjb) * C;
                        if (tt > lmax) lmax = tt;
                    }
                }
            }
        }
        if (ll > ih) {  // upper segments cover [lcm[ih], lcm[ll]]
            int A = g_lcm[ih], B = g_lcm[ll];
            int total = B - A + 1;
            int per = (total + 1023) / 1024;
            int lo = A + tid * per;
            int hi = lo + per - 1; if (hi > B) hi = B;
            if (lo <= hi) {
                int nseg = ll - ih;
                int lo2 = 0, hi2 = nseg - 1;
                while (lo2 < hi2) {
                    int mid = (lo2 + hi2 + 1) >> 1;
                    if (g_lcm[ih + mid] <= lo) lo2 = mid; else hi2 = mid - 1;
                }
                int t = lo2;
                int jb = g_lcm[ih + t], je = g_lcm[ih + t + 1];
                double xjb = g_xs[jb], xje = g_xs[je];
                bool valid = (je - jb > 1) && (xje != xjb);
                double C = valid ? (double)(je - jb) / (xje - xjb) : 0.0;
                for (int i = lo; i <= hi; i++) {
                    while (i > je && t < nseg - 1) {
                        t++; jb = je; xjb = xje;
                        je = g_lcm[ih + t + 1]; xje = g_xs[je];
                        valid = (je - jb > 1) && (xje != xjb);
                        C = valid ? (double)(je - jb) / (xje - xjb) : 0.0;
                    }
                    if (valid) {
                        double tt = (g_xs[i] - xjb) * C - (double)(i - jb - 1);
                        if (tt > umax) umax = tt;
                    }
                }
            }
        }

        double rl = block_max(lmax, red, tid);
        double ru = block_max(umax, red, tid);

        if (tid == 0) {
            double dl = (lg > ig) ? ((rl > 1.0) ? rl : 1.0) : 0.0;
            double du = (ll > ih) ? ((ru > 1.0) ? ru : 1.0) : 0.0;
            double dn = (du > dl) ? du : dl;
            if (s_dip < dn) s_dip = dn;
            int nl = g_gcm[s_ig], nh = g_lcm[s_ih];
            if (s_low == nl && s_high == nh) s_done = 1;
            else { s_low = nl; s_high = nh; }
        }
        __syncthreads();
        if (s_done) break;
    }
    __syncthreads();
    if (tid == 0) out[0] = (float)(s_dip / (2.0 * (double)N));
}

// ---------------------------------------------------------------------------
extern "C" void kernel_launch(void* const* d_in, const int* in_sizes, int n_in,
                              void* d_out, int out_size) {
    const float* X   = (const float*)d_in[0];
    const float* PV  = (const float*)d_in[1];
    const int*   IDX = (const int*)d_in[2];

    const int D = 128;
    int N = in_sizes[0] / D;
    if (N <= 0 || N > MAXN) return;

    float* proj = nullptr;
    float* sorted = nullptr;
    void*  tmp = nullptr;
    cudaGetSymbolAddress((void**)&proj, g_proj);
    cudaGetSymbolAddress((void**)&sorted, g_sorted);
    cudaGetSymbolAddress(&tmp, g_cub_tmp);

    k_matvec<<<(N * 32 + 255) / 256, 256>>>(X, PV, IDX, N);

    size_t tb = 0;
    cub::DeviceRadixSort::SortKeys(nullptr, tb, proj, sorted, N);
    if (tb > sizeof(g_cub_tmp)) return;
    cub::DeviceRadixSort::SortKeys(tmp, tb, proj, sorted, N);

    k_convert<<<(N + 255) / 256, 256>>>(N);

    int nchunk = (N + CH - 1) / CH;
    k_chunk_hulls<<<nchunk, 64>>>(N);

    k_dip<<<1, 1024>>>(N, (float*)d_out);
}

// round 4
// speedup vs baseline: 2.2338x; 2.2338x over previous
#include <cuda_runtime.h>
#include <cuda_bf16.h>
#include <cub/cub.cuh>

#define CH 1024
#define SC 16
#define SCAP 1800
constexpr int MAXN = 1 << 18;
constexpr int MAXC = MAXN / CH;
constexpr int MAXS = (MAXC + SC - 1) / SC;
constexpr int CAP  = 6144;
constexpr int DYN_BYTES = CAP * 8 * 2 + 1024 * 8 + CAP * 4 * 2;  // 155648

__device__ float  g_proj[MAXN];
__device__ float  g_sorted[MAXN];
__device__ double g_xs[MAXN + 2];
__device__ int    g_lh_idx[MAXN];
__device__ double g_lh_val[MAXN];
__device__ int    g_lhn[MAXC];
__device__ int    g_uh_idx[MAXN];
__device__ double g_uh_val[MAXN];
__device__ int    g_uhn[MAXC];
__device__ int    g_slh_idx[MAXN];
__device__ double g_slh_val[MAXN];
__device__ int    g_slhn[MAXS];
__device__ int    g_suh_idx[MAXN];
__device__ double g_suh_val[MAXN];
__device__ int    g_suhn[MAXS];
__device__ int    g_Hidx[MAXN + 2];     // fallback scratch (lower)
__device__ double g_Hval[MAXN + 2];
__device__ int    g_Sidx[MAXN + 2];     // fallback scratch (upper)
__device__ double g_Sval[MAXN + 2];
__device__ unsigned char g_cub_tmp[1 << 24];

// ---------------- matvec: one warp per row, D=128 ----------------
__global__ void k_matvec(const float* __restrict__ X, const float* __restrict__ PV,
                         const int* __restrict__ IDX, int N) {
    __shared__ __align__(16) float sp[128];
    int pidx = IDX[0];
    if (threadIdx.x < 128) sp[threadIdx.x] = PV[pidx * 128 + threadIdx.x];
    __syncthreads();
    int g    = blockIdx.x * blockDim.x + threadIdx.x;
    int row  = g >> 5;
    int lane = g & 31;
    if (row >= N) return;
    const float4* xr = reinterpret_cast<const float4*>(X) + (size_t)row * 32;
    float4 a = xr[lane];
    float4 b = reinterpret_cast<const float4*>(sp)[lane];
    float s = a.x * b.x + a.y * b.y + a.z * b.z + a.w * b.w;
#pragma unroll
    for (int o = 16; o; o >>= 1) s += __shfl_xor_sync(0xffffffffu, s, o);
    if (lane == 0) g_proj[row] = s;
}

__global__ void k_convert(int N) {
    int i = blockIdx.x * blockDim.x + threadIdx.x;
    if (i < N) g_xs[i + 1] = (double)g_sorted[i];
    if (i == 0) g_xs[0] = 0.0;
}

// In-place strict monotone-chain over pre-staged candidates (processing order).
// Pop inequality is the exact reference one (equality pops collinear points).
// Works for the upper hull when candidates are in decreasing-index order.
// In-place safe: stack write position m <= read position r always.
__device__ __forceinline__ int merge_inplace(int* idx, double* val, int n) {
    int m = 0, ai = 0, bi = 0; double av = 0.0, bv = 0.0;
    for (int r = 0; r < n; r++) {
        int ci = idx[r]; double cv = val[r];
        while (m >= 2) {
            if ((cv - bv) * (double)(bi - ai) < (bv - av) * (double)(ci - bi)) break;
            m--; bi = ai; bv = av;
            if (m >= 2) { ai = idx[m - 2]; av = val[m - 2]; }
        }
        idx[m] = ci; val[m] = cv;
        ai = bi; av = bv; bi = ci; bv = cv; m++;
    }
    return m;
}

// Per-chunk strict hulls, all in shared memory.
__global__ void k_chunk_hulls(int N) {
    __shared__ int    sliL[CH]; __shared__ double slvL[CH];
    __shared__ int    sliU[CH]; __shared__ double slvU[CH];
    __shared__ int smL, smU;
    int c = blockIdx.x, tid = threadIdx.x;
    int s = c * CH + 1;
    int e = min((c + 1) * CH, N);
    int n = e - s + 1;
    for (int k = tid; k < n; k += blockDim.x) {
        double v = g_xs[s + k];
        sliL[k] = s + k;       slvL[k] = v;
        sliU[n - 1 - k] = s + k; slvU[n - 1 - k] = v;   // descending order
    }
    __syncthreads();
    if (tid == 0)  smL = merge_inplace(sliL, slvL, n);
    if (tid == 64) smU = merge_inplace(sliU, slvU, n);
    __syncthreads();
    int base = c * CH;
    for (int k = tid; k < smL; k += blockDim.x) { g_lh_idx[base + k] = sliL[k]; g_lh_val[base + k] = slvL[k]; }
    for (int k = tid; k < smU; k += blockDim.x) { g_uh_idx[base + k] = sliU[k]; g_uh_val[base + k] = slvU[k]; }
    if (tid == 0)  g_lhn[c] = smL;
    if (tid == 64) g_uhn[c] = smU;
}

// Superchunk hulls: merge SC chunk hulls (done once).
__global__ void k_super_hulls(int N, int nchunk) {
    __shared__ int    sIdx0[SCAP]; __shared__ double sVal0[SCAP];
    __shared__ int    sIdx1[SCAP]; __shared__ double sVal1[SCAP];
    __shared__ int offL[SC + 1], offU[SC + 1];
    __shared__ int totL, totU, mL, mU;
    __shared__ int* pIL; __shared__ double* pVL; __shared__ int* pIU; __shared__ double* pVU;
    int sblk = blockIdx.x, tid = threadIdx.x;
    int c0 = sblk * SC;
    int c1 = min(c0 + SC, nchunk);
    int nc = c1 - c0;
    int gbase = c0 * CH;
    if (tid == 0) {
        int o = 0;
        for (int c = c0; c < c1; c++) { offL[c - c0] = o; o += g_lhn[c]; }
        totL = o;
        pIL = (o <= SCAP) ? sIdx0 : (g_slh_idx + gbase);
        pVL = (o <= SCAP) ? sVal0 : (g_slh_val + gbase);
    }
    if (tid == 32) {
        int o = 0;
        for (int c = c1 - 1; c >= c0; c--) { offU[c1 - 1 - c] = o; o += g_uhn[c]; }
        totU = o;
        pIU = (o <= SCAP) ? sIdx1 : (g_suh_idx + gbase);
        pVU = (o <= SCAP) ? sVal1 : (g_suh_val + gbase);
    }
    __syncthreads();
    for (int j = 0; j < nc; j++) {
        int c = c0 + j;
        int srcb = c * CH, len = g_lhn[c], dst = offL[j];
        for (int k = tid; k < len; k += blockDim.x) { pIL[dst + k] = g_lh_idx[srcb + k]; pVL[dst + k] = g_lh_val[srcb + k]; }
        int cu = c1 - 1 - j;
        int srcbu = cu * CH, lenu = g_uhn[cu], dstu = offU[j];
        for (int k = tid; k < lenu; k += blockDim.x) { pIU[dstu + k] = g_uh_idx[srcbu + k]; pVU[dstu + k] = g_uh_val[srcbu + k]; }
    }
    __syncthreads();
    if (tid == 0)  mL = merge_inplace(pIL, pVL, totL);
    if (tid == 32) mU = merge_inplace(pIU, pVU, totU);
    __syncthreads();
    for (int k = tid; k < mL; k += blockDim.x) { g_slh_idx[gbase + k] = pIL[k]; g_slh_val[gbase + k] = pVL[k]; }
    for (int k = tid; k < mU; k += blockDim.x) { g_suh_idx[gbase + k] = pIU[k]; g_suh_val[gbase + k] = pVU[k]; }
    if (tid == 0)  g_slhn[sblk] = mL;
    if (tid == 32) g_suhn[sblk] = mU;
}

__device__ __forceinline__ double block_max(double v, double* red, int tid) {
    red[tid] = v;
    __syncthreads();
    for (int s = 512; s > 0; s >>= 1) {
        if (tid < s) { double o = red[tid + s]; if (o > red[tid]) red[tid] = o; }
        __syncthreads();
    }
    double r = red[0];
    __syncthreads();
    return r;
}

__global__ void __launch_bounds__(1024, 1) k_dip(int N, int nchunk, int nsuper, float* out) {
    extern __shared__ unsigned char dyn[];
    double* dValL = (double*)dyn;                 // CAP
    double* dValU = dValL + CAP;                  // CAP
    double* red   = dValU + CAP;                  // 1024
    int*    dIdxL = (int*)(red + 1024);           // CAP
    int*    dIdxU = dIdxL + CAP;                  // CAP

    __shared__ int s_low, s_high, s_done;
    __shared__ double s_dip;
    __shared__ int nsL, nsU, totL, totU, s_mL, s_mU, s_lg, s_ll, s_ig, s_ih;
    __shared__ int4 srcL[40], srcU[40];
    __shared__ int* pIL; __shared__ double* pVL; __shared__ int* pIU; __shared__ double* pVU;

    int tid = threadIdx.x;
    if (tid == 0) { s_low = 1; s_high = N; s_dip = 1.0; s_done = 0; }
    __syncthreads();
    if (N < 4 || g_xs[1] == g_xs[N]) {
        if (tid == 0) out[0] = (float)(1.0 / (2.0 * (double)(N > 0 ? N : 1)));
        return;
    }

    for (int iter = 0; iter < 64; iter++) {
        int low = s_low, high = s_high;

        // -------- source lists --------
        if (tid == 0) {
            int hc = (high - 1) / CH;
            int sc = hc / SC;
            int ns = 0, o = 0;
            for (int s = 0; s < sc; s++)         { int l = g_slhn[s]; srcL[ns] = make_int4(1, s * SC * CH, l, o); ns++; o += l; }
            for (int c = sc * SC; c < hc; c++)   { int l = g_lhn[c];  srcL[ns] = make_int4(0, c * CH, l, o); ns++; o += l; }
            int rb = hc * CH + 1, rl = high - hc * CH;
            srcL[ns] = make_int4(2, rb, rl, o); ns++; o += rl;
            nsL = ns; totL = o;
            pIL = (o <= CAP) ? dIdxL : g_Hidx;
            pVL = (o <= CAP) ? dValL : g_Hval;
        }
        if (tid == 32) {
            int lc = (low - 1) / CH;
            int scU = (lc + SC) / SC;                        // ceil((lc+1)/SC)
            int ns = 0, o = 0;
            for (int s = nsuper - 1; s >= scU; s--) { int l = g_suhn[s]; srcU[ns] = make_int4(4, s * SC * CH, l, o); ns++; o += l; }
            int ctop = min(scU * SC, nchunk) - 1;
            for (int c = ctop; c >= lc + 1; c--)    { int l = g_uhn[c];  srcU[ns] = make_int4(3, c * CH, l, o); ns++; o += l; }
            int rb = min((lc + 1) * CH, N), rl = rb - low + 1;
            srcU[ns] = make_int4(5, rb, rl, o); ns++; o += rl;
            nsU = ns; totU = o;
            pIU = (o <= CAP) ? dIdxU : g_Sidx;
            pVU = (o <= CAP) ? dValU : g_Sval;
        }
        __syncthreads();

        // -------- stage candidates (all threads) --------
        {
            int* IL = pIL; double* VL = pVL;
            for (int j = 0; j < nsL; j++) {
                int4 sd = srcL[j];
                if (sd.x == 2)       for (int k = tid; k < sd.z; k += 1024) { IL[sd.w + k] = sd.y + k;           VL[sd.w + k] = g_xs[sd.y + k]; }
                else if (sd.x == 0)  for (int k = tid; k < sd.z; k += 1024) { IL[sd.w + k] = g_lh_idx[sd.y + k]; VL[sd.w + k] = g_lh_val[sd.y + k]; }
                else                 for (int k = tid; k < sd.z; k += 1024) { IL[sd.w + k] = g_slh_idx[sd.y + k]; VL[sd.w + k] = g_slh_val[sd.y + k]; }
            }
            int* IU = pIU; double* VU = pVU;
            for (int j = 0; j < nsU; j++) {
                int4 sd = srcU[j];
                if (sd.x == 5)       for (int k = tid; k < sd.z; k += 1024) { IU[sd.w + k] = sd.y - k;           VU[sd.w + k] = g_xs[sd.y - k]; }
                else if (sd.x == 3)  for (int k = tid; k < sd.z; k += 1024) { IU[sd.w + k] = g_uh_idx[sd.y + k]; VU[sd.w + k] = g_uh_val[sd.y + k]; }
                else                 for (int k = tid; k < sd.z; k += 1024) { IU[sd.w + k] = g_suh_idx[sd.y + k]; VU[sd.w + k] = g_suh_val[sd.y + k]; }
            }
        }
        __syncthreads();

        // -------- merges + chain truncation --------
        if (tid == 0) {
            int m = merge_inplace(pIL, pVL, totL);
            int lo2 = 0, hi2 = m - 1;
            while (lo2 < hi2) { int mid = (lo2 + hi2 + 1) >> 1; if (pIL[mid] <= low) lo2 = mid; else hi2 = mid - 1; }
            s_mL = m; s_lg = m - lo2;
        }
        if (tid == 32) {
            int m = merge_inplace(pIU, pVU, totU);
            int lo2 = 0, hi2 = m - 1;
            while (lo2 < hi2) { int mid = (lo2 + hi2 + 1) >> 1; if (pIU[mid] >= high) lo2 = mid; else hi2 = mid - 1; }
            s_mU = m; s_ll = m - lo2;
        }
        __syncthreads();

        int mL = s_mL, mU = s_mU, lg = s_lg, ll = s_ll;
        // chain mapping: gcm[i] = pIL[mL - i] (i=1..lg), lcm[i] = pIU[mU - i] (i=1..ll)

        // -------- d-walk (verbatim reference port) --------
        if (tid == 0) {
            int ig = lg, ih = ll, ix = lg - 1, iv = 2;
            double d = 0.0;
            if (!(lg == 2 && ll == 2)) {
                long long guard = 4LL * N + 16;
                while (guard-- > 0) {
                    int gcmix = pIL[mL - ix], lcmiv = pIU[mU - iv];
                    if (gcmix > lcmiv) {
                        int gcmi1 = pIL[mL - ix - 1];
                        double xg = pVL[mL - ix], xg1 = pVL[mL - ix - 1], xl = pVU[mU - iv];
                        double t = (double)(lcmiv - gcmi1 + 1) - (xl - xg1) * (double)(gcmix - gcmi1) / (xg - xg1);
                        iv++;
                        if (t >= d) { d = t; ig = ix + 1; ih = iv - 1; }
                    } else {
                        int lcmiv1 = pIU[mU - iv + 1];
                        double xg = pVL[mL - ix], xl = pVU[mU - iv], xl1 = pVU[mU - iv + 1];
                        double t = (xg - xl1) * (double)(lcmiv - lcmiv1) / (xl - xl1) - (double)(gcmix - lcmiv1 - 1);
                        ix--;
                        if (t > d) { d = t; ig = ix + 1; ih = iv; }
                    }
                    if (ix < 1) ix = 1;
                    if (iv > ll) iv = ll;
                    if (pIL[mL - ix] == pIU[mU - iv]) break;
                }
            } else d = 1.0;
            s_ig = ig; s_ih = ih;
            if (d < s_dip) s_done = 1;
        }
        __syncthreads();
        if (s_done) break;

        // -------- fused parallel segment scans --------
        int ig = s_ig, ih = s_ih;
        double lmax = -1e308, umax = -1e308;

        if (lg > ig) {   // segments t: jb=pIL[base+t], je=pIL[base+t+1]; covers [gcm[lg], gcm[ig]]
            int base = mL - lg;
            int nseg = lg - ig;
            int A = pIL[base], B = pIL[base + nseg];
            int total = B - A + 1;
            int per = (total + 1023) / 1024;
            int lo = A + tid * per;
            int hi = min(lo + per - 1, B);
            if (lo <= hi) {
                int lo2 = 0, hi2 = nseg - 1;
                while (lo2 < hi2) { int mid = (lo2 + hi2 + 1) >> 1; if (pIL[base + mid] <= lo) lo2 = mid; else hi2 = mid - 1; }
                int t = lo2;
                int jb = pIL[base + t], je = pIL[base + t + 1];
                double xjb = pVL[base + t], xje = pVL[base + t + 1];
                bool valid = (je - jb > 1) && (xje != xjb);
                double C = valid ? (double)(je - jb) / (xje - xjb) : 0.0;
                for (int i = lo; i <= hi; i++) {
                    while (i > je && t < nseg - 1) {
                        t++; jb = je; xjb = xje;
                        je = pIL[base + t + 1]; xje = pVL[base + t + 1];
                        valid = (je - jb > 1) && (xje != xjb);
                        C = valid ? (double)(je - jb) / (xje - xjb) : 0.0;
                    }
                    if (valid) {
                        double tt = (double)(i - jb + 1) - (g_xs[i] - xjb) * C;
                        if (tt > lmax) lmax = tt;
                    }
                }
            }
        }
        if (ll > ih) {   // segments t: jb=pIU[baseU-t], je=pIU[baseU-t-1]; covers [lcm[ih], lcm[ll]]
            int baseU = mU - ih;
            int nseg = ll - ih;
            int A = pIU[baseU], B = pIU[baseU - nseg];
            int total = B - A + 1;
            int per = (total + 1023) / 1024;
            int lo = A + tid * per;
            int hi = min(lo + per - 1, B);
            if (lo <= hi) {
                int lo2 = 0, hi2 = nseg - 1;
                while (lo2 < hi2) { int mid = (lo2 + hi2 + 1) >> 1; if (pIU[baseU - mid] <= lo) lo2 = mid; else hi2 = mid - 1; }
                int t = lo2;
                int jb = pIU[baseU - t], je = pIU[baseU - t - 1];
                double xjb = pVU[baseU - t], xje = pVU[baseU - t - 1];
                bool valid = (je - jb > 1) && (xje != xjb);
                double C = valid ? (double)(je - jb) / (xje - xjb) : 0.0;
                for (int i = lo; i <= hi; i++) {
                    while (i > je && t < nseg - 1) {
                        t++; jb = je; xjb = xje;
                        je = pIU[baseU - t - 1]; xje = pVU[baseU - t - 1];
                        valid = (je - jb > 1) && (xje != xjb);
                        C = valid ? (double)(je - jb) / (xje - xjb) : 0.0;
                    }
                    if (valid) {
                        double tt = (g_xs[i] - xjb) * C - (double)(i - jb - 1);
                        if (tt > umax) umax = tt;
                    }
                }
            }
        }

        double rl = block_max(lmax, red, tid);
        double ru = block_max(umax, red, tid);

        if (tid == 0) {
            double dl = (lg > ig) ? ((rl > 1.0) ? rl : 1.0) : 0.0;
            double du = (ll > ih) ? ((ru > 1.0) ? ru : 1.0) : 0.0;
            double dn = (du > dl) ? du : dl;
            if (s_dip < dn) s_dip = dn;
            int nl = pIL[mL - s_ig], nh = pIU[mU - s_ih];
            if ((s_low == nl && s_high == nh) || nl >= nh) s_done = 1;
            else { s_low = nl; s_high = nh; }
        }
        __syncthreads();
        if (s_done) break;
    }
    __syncthreads();
    if (tid == 0) out[0] = (float)(s_dip / (2.0 * (double)N));
}

// ---------------------------------------------------------------------------
extern "C" void kernel_launch(void* const* d_in, const int* in_sizes, int n_in,
                              void* d_out, int out_size) {
    const float* X   = (const float*)d_in[0];
    const float* PV  = (const float*)d_in[1];
    const int*   IDX = (const int*)d_in[2];

    const int D = 128;
    int N = in_sizes[0] / D;
    if (N <= 0 || N > MAXN) return;

    float* proj = nullptr;
    float* sorted = nullptr;
    void*  tmp = nullptr;
    cudaGetSymbolAddress((void**)&proj, g_proj);
    cudaGetSymbolAddress((void**)&sorted, g_sorted);
    cudaGetSymbolAddress(&tmp, g_cub_tmp);

    static bool attr_done = false;
    if (!attr_done) {
        cudaFuncSetAttribute(k_dip, cudaFuncAttributeMaxDynamicSharedMemorySize, DYN_BYTES);
        attr_done = true;
    }

    k_matvec<<<(N * 32 + 255) / 256, 256>>>(X, PV, IDX, N);

    size_t tb = 0;
    cub::DeviceRadixSort::SortKeys(nullptr, tb, proj, sorted, N);
    if (tb > sizeof(g_cub_tmp)) return;
    cub::DeviceRadixSort::SortKeys(tmp, tb, proj, sorted, N);

    k_convert<<<(N + 255) / 256, 256>>>(N);

    int nchunk = (N + CH - 1) / CH;
    int nsuper = (nchunk + SC - 1) / SC;
    k_chunk_hulls<<<nchunk, 128>>>(N);
    k_super_hulls<<<nsuper, 256>>>(N, nchunk);

    k_dip<<<1, 1024, DYN_BYTES>>>(N, nchunk, nsuper, (float*)d_out);
}